// round 1
// baseline (speedup 1.0000x reference)
#include <cuda_runtime.h>

#define N_NODES 50000
#define NNZ     800000
#define S       3
#define D_IN    512
#define D_OUT   256

// 3 * 50000 * 256 floats = 153.6 MB scratch for pre[s] = cw[s] * (x @ W[s])
__device__ float g_pre[(size_t)S * N_NODES * D_OUT];

// ---------------------------------------------------------------------------
// SGEMM: pre[s] = cw[s] * (x @ W[s]).  M=50000, K=512, N=256.
// 128x128 tile, BK=8, 256 threads, 8x8 microtile (split 4+4 rows / 4+4 cols),
// double-buffered SMEM.
// ---------------------------------------------------------------------------
__global__ __launch_bounds__(256) void gemm_kernel(
    const float* __restrict__ x,
    const float* __restrict__ W,
    const float* __restrict__ cw)
{
    __shared__ float As[2][8][132];   // transposed A tile, padded
    __shared__ float Bs[2][8][132];

    const int s         = blockIdx.z;
    const int block_row = blockIdx.y * 128;
    const int block_col = blockIdx.x * 128;
    const int tid       = threadIdx.x;

    const float* B   = W + (size_t)s * D_IN * D_OUT;
    float*       dst = g_pre + (size_t)s * N_NODES * D_OUT;

    // global load mapping
    const int a_row = tid >> 1;          // 0..127
    const int a_col = (tid & 1) * 4;     // 0 or 4
    const int b_row = tid >> 5;          // 0..7
    const int b_col = (tid & 31) * 4;    // 0..124

    const int  g_arow  = block_row + a_row;
    const bool a_valid = (g_arow < N_NODES);
    const float* Aptr  = x + (size_t)(a_valid ? g_arow : 0) * D_IN + a_col;
    const float* Bptr  = B + (size_t)b_row * D_OUT + block_col + b_col;

    // compute mapping: ty in 0..15 (rows), tx in 0..15 (cols)
    const int ty = tid >> 4;
    const int tx = tid & 15;

    float acc[8][8];
#pragma unroll
    for (int i = 0; i < 8; i++)
#pragma unroll
        for (int j = 0; j < 8; j++) acc[i][j] = 0.0f;

    // preload k-tile 0
    {
        float4 av = *(const float4*)(Aptr);
        float4 bv = *(const float4*)(Bptr);
        if (!a_valid) av = make_float4(0.f, 0.f, 0.f, 0.f);
        As[0][a_col + 0][a_row] = av.x;
        As[0][a_col + 1][a_row] = av.y;
        As[0][a_col + 2][a_row] = av.z;
        As[0][a_col + 3][a_row] = av.w;
        *(float4*)&Bs[0][b_row][b_col] = bv;
    }
    __syncthreads();

    int buf = 0;
    for (int k0 = 0; k0 < D_IN; k0 += 8) {
        const bool has_next = (k0 + 8) < D_IN;
        float4 an, bn;
        if (has_next) {
            an = *(const float4*)(Aptr + k0 + 8);
            if (!a_valid) an = make_float4(0.f, 0.f, 0.f, 0.f);
            bn = *(const float4*)(Bptr + (size_t)(k0 + 8) * D_OUT);
        }

#pragma unroll
        for (int kk = 0; kk < 8; kk++) {
            float4 a0 = *(const float4*)&As[buf][kk][ty * 4];
            float4 a1 = *(const float4*)&As[buf][kk][64 + ty * 4];
            float4 b0 = *(const float4*)&Bs[buf][kk][tx * 4];
            float4 b1 = *(const float4*)&Bs[buf][kk][64 + tx * 4];
            float ra[8] = {a0.x, a0.y, a0.z, a0.w, a1.x, a1.y, a1.z, a1.w};
            float rb[8] = {b0.x, b0.y, b0.z, b0.w, b1.x, b1.y, b1.z, b1.w};
#pragma unroll
            for (int i = 0; i < 8; i++)
#pragma unroll
                for (int j = 0; j < 8; j++)
                    acc[i][j] = fmaf(ra[i], rb[j], acc[i][j]);
        }

        if (has_next) {
            const int nb = buf ^ 1;
            As[nb][a_col + 0][a_row] = an.x;
            As[nb][a_col + 1][a_row] = an.y;
            As[nb][a_col + 2][a_row] = an.z;
            As[nb][a_col + 3][a_row] = an.w;
            *(float4*)&Bs[nb][b_row][b_col] = bn;
        }
        __syncthreads();
        buf ^= 1;
    }

    const float scale = __ldg(cw + s);

#pragma unroll
    for (int ih = 0; ih < 2; ih++) {
#pragma unroll
        for (int i = 0; i < 4; i++) {
            const int r = block_row + ih * 64 + ty * 4 + i;
            if (r < N_NODES) {
                float* o = dst + (size_t)r * D_OUT + block_col;
                const int ai = ih * 4 + i;
                float4 v0 = make_float4(acc[ai][0] * scale, acc[ai][1] * scale,
                                        acc[ai][2] * scale, acc[ai][3] * scale);
                float4 v1 = make_float4(acc[ai][4] * scale, acc[ai][5] * scale,
                                        acc[ai][6] * scale, acc[ai][7] * scale);
                *(float4*)(o + tx * 4)      = v0;
                *(float4*)(o + 64 + tx * 4) = v1;
            }
        }
    }
}

// ---------------------------------------------------------------------------
// SpMM scatter: out[r] += v * pre[s][c].  64 lanes per nnz, one float4 each,
// vectorized global reduction (red.global.add.v4.f32).
// ---------------------------------------------------------------------------
__global__ __launch_bounds__(256) void spmm_kernel(
    const int*   __restrict__ rows,
    const int*   __restrict__ cols,
    const float* __restrict__ vals,
    float*       __restrict__ out)
{
    const int idx  = blockIdx.x * 4 + (threadIdx.x >> 6);  // nnz index in [0, S*NNZ)
    const int lane = threadIdx.x & 63;

    const int   r = rows[idx];
    const int   c = cols[idx];
    const float v = vals[idx];
    const int   s = idx / NNZ;

    const float4 p =
        *((const float4*)(g_pre + ((size_t)s * N_NODES + c) * D_OUT) + lane);

    float* dst = out + (size_t)r * D_OUT + lane * 4;
    asm volatile("red.global.add.v4.f32 [%0], {%1, %2, %3, %4};"
                 :: "l"(dst), "f"(p.x * v), "f"(p.y * v), "f"(p.z * v), "f"(p.w * v)
                 : "memory");
}

// ---------------------------------------------------------------------------
// Zero + ReLU
// ---------------------------------------------------------------------------
__global__ __launch_bounds__(256) void zero_kernel(float4* __restrict__ out)
{
    out[(size_t)blockIdx.x * 256 + threadIdx.x] = make_float4(0.f, 0.f, 0.f, 0.f);
}

__global__ __launch_bounds__(256) void relu_kernel(float4* __restrict__ out)
{
    const size_t i = (size_t)blockIdx.x * 256 + threadIdx.x;
    float4 v = out[i];
    v.x = fmaxf(v.x, 0.f);
    v.y = fmaxf(v.y, 0.f);
    v.z = fmaxf(v.z, 0.f);
    v.w = fmaxf(v.w, 0.f);
    out[i] = v;
}

// ---------------------------------------------------------------------------
// Launch
// ---------------------------------------------------------------------------
extern "C" void kernel_launch(void* const* d_in, const int* in_sizes, int n_in,
                              void* d_out, int out_size)
{
    const float* x    = (const float*)d_in[0];
    const float* W    = (const float*)d_in[1];
    const int*   rows = (const int*)d_in[2];
    const int*   cols = (const int*)d_in[3];
    const float* vals = (const float*)d_in[4];
    const float* cw   = (const float*)d_in[5];
    float*       out  = (float*)d_out;

    // out is 50000*256 = 12,800,000 floats = 3,200,000 float4 = 12500 blocks of 256
    zero_kernel<<<12500, 256>>>((float4*)out);

    dim3 ggrid(D_OUT / 128, (N_NODES + 127) / 128, S);  // (2, 391, 3)
    gemm_kernel<<<ggrid, 256>>>(x, W, cw);

    spmm_kernel<<<(S * NNZ) / 4, 256>>>(rows, cols, vals, out);

    relu_kernel<<<12500, 256>>>((float4*)out);
}

// round 2
// speedup vs baseline: 1.3268x; 1.3268x over previous
#include <cuda_runtime.h>

#define N_NODES 50000
#define NNZ     800000
#define S       3
#define D_IN    512
#define D_OUT   256

// 3 * 50000 * 256 floats = 153.6 MB scratch for pre[s] = cw[s] * (x @ W[s])
__device__ float g_pre[(size_t)S * N_NODES * D_OUT];

// ---------------------------------------------------------------------------
// tf32 tensor-core GEMM: pre[s] = cw[s] * (x @ W[s]).  M=50000, K=512, N=256.
// 128x128 tile, BK=16, 256 threads (8 warps, 2x4), warp tile 64x32,
// mma.sync.m16n8k8.tf32, double-buffered SMEM with conflict-free strides.
// ---------------------------------------------------------------------------
#define BM 128
#define BN 128
#define BK 16
#define A_STRIDE 20    // (20*g + t) mod 32 covers all banks for frag loads
#define B_STRIDE 136   // 136 mod 32 == 8 -> (8*k' + g) covers all banks

__device__ __forceinline__ float f2tf32(float x)
{
    asm("cvt.rna.tf32.f32 %0, %0;" : "+f"(x));
    return x;
}

__device__ __forceinline__ void mma_tf32(float c[4], const float a[4], const float b[2])
{
    asm volatile(
        "mma.sync.aligned.m16n8k8.row.col.f32.tf32.tf32.f32 "
        "{%0,%1,%2,%3}, {%4,%5,%6,%7}, {%8,%9}, {%0,%1,%2,%3};\n"
        : "+f"(c[0]), "+f"(c[1]), "+f"(c[2]), "+f"(c[3])
        : "r"(__float_as_uint(a[0])), "r"(__float_as_uint(a[1])),
          "r"(__float_as_uint(a[2])), "r"(__float_as_uint(a[3])),
          "r"(__float_as_uint(b[0])), "r"(__float_as_uint(b[1])));
}

__global__ __launch_bounds__(256) void gemm_tf32_kernel(
    const float* __restrict__ x,
    const float* __restrict__ W,
    const float* __restrict__ cw)
{
    __shared__ float As[2][BM * A_STRIDE];
    __shared__ float Bs[2][BK * B_STRIDE];

    const int s         = blockIdx.z;
    const int block_row = blockIdx.y * BM;
    const int block_col = blockIdx.x * BN;
    const int tid       = threadIdx.x;
    const int lane      = tid & 31;
    const int wid       = tid >> 5;
    const int warp_m    = wid >> 2;  // 0..1
    const int warp_n    = wid & 3;   // 0..3

    const float* Bg = W + (size_t)s * D_IN * D_OUT;

    // A gmem mapping: row = tid>>1 (0..127), k-col = (tid&1)*8 (+0/+4)
    const int a_row  = tid >> 1;
    const int a_kcol = (tid & 1) * 8;
    int g_arow = block_row + a_row;
    const bool a_valid = (g_arow < N_NODES);
    if (!a_valid) g_arow = 0;
    const float* Aptr = x + (size_t)g_arow * D_IN + a_kcol;

    // B gmem mapping: k-row = tid>>4 (0..15), n-col = (tid&15)*8 (+0/+4)
    const int b_krow = tid >> 4;
    const int b_ncol = (tid & 15) * 8;
    const float* Bptr = Bg + (size_t)b_krow * D_OUT + block_col + b_ncol;

    float c[4][4][4];
#pragma unroll
    for (int mt = 0; mt < 4; mt++)
#pragma unroll
        for (int nt = 0; nt < 4; nt++)
#pragma unroll
            for (int i = 0; i < 4; i++) c[mt][nt][i] = 0.0f;

    float4 a0r, a1r, b0r, b1r;

    // prefetch tile 0
    a0r = *(const float4*)(Aptr);
    a1r = *(const float4*)(Aptr + 4);
    if (!a_valid) { a0r = make_float4(0,0,0,0); a1r = make_float4(0,0,0,0); }
    b0r = *(const float4*)(Bptr);
    b1r = *(const float4*)(Bptr + 4);

    // store tile 0
    {
        float* pa = &As[0][a_row * A_STRIDE + a_kcol];
        pa[0] = f2tf32(a0r.x); pa[1] = f2tf32(a0r.y);
        pa[2] = f2tf32(a0r.z); pa[3] = f2tf32(a0r.w);
        pa[4] = f2tf32(a1r.x); pa[5] = f2tf32(a1r.y);
        pa[6] = f2tf32(a1r.z); pa[7] = f2tf32(a1r.w);
        float* pb = &Bs[0][b_krow * B_STRIDE + b_ncol];
        pb[0] = f2tf32(b0r.x); pb[1] = f2tf32(b0r.y);
        pb[2] = f2tf32(b0r.z); pb[3] = f2tf32(b0r.w);
        pb[4] = f2tf32(b1r.x); pb[5] = f2tf32(b1r.y);
        pb[6] = f2tf32(b1r.z); pb[7] = f2tf32(b1r.w);
    }
    __syncthreads();

    int buf = 0;
    for (int k0 = 0; k0 < D_IN; k0 += BK) {
        const bool has_next = (k0 + BK) < D_IN;
        if (has_next) {
            a0r = *(const float4*)(Aptr + k0 + BK);
            a1r = *(const float4*)(Aptr + k0 + BK + 4);
            if (!a_valid) { a0r = make_float4(0,0,0,0); a1r = make_float4(0,0,0,0); }
            b0r = *(const float4*)(Bptr + (size_t)(k0 + BK) * D_OUT);
            b1r = *(const float4*)(Bptr + (size_t)(k0 + BK) * D_OUT + 4);
        }

#pragma unroll
        for (int kk = 0; kk < BK; kk += 8) {
            float a[4][4];
            float b[4][2];
            const int kb = kk + (lane & 3);
#pragma unroll
            for (int mt = 0; mt < 4; mt++) {
                const int rb = warp_m * 64 + mt * 16 + (lane >> 2);
                const float* base = &As[buf][0];
                a[mt][0] = base[rb * A_STRIDE + kb];
                a[mt][1] = base[(rb + 8) * A_STRIDE + kb];
                a[mt][2] = base[rb * A_STRIDE + kb + 4];
                a[mt][3] = base[(rb + 8) * A_STRIDE + kb + 4];
            }
#pragma unroll
            for (int nt = 0; nt < 4; nt++) {
                const int nb = warp_n * 32 + nt * 8 + (lane >> 2);
                b[nt][0] = Bs[buf][kb * B_STRIDE + nb];
                b[nt][1] = Bs[buf][(kb + 4) * B_STRIDE + nb];
            }
#pragma unroll
            for (int mt = 0; mt < 4; mt++)
#pragma unroll
                for (int nt = 0; nt < 4; nt++)
                    mma_tf32(c[mt][nt], a[mt], b[nt]);
        }

        if (has_next) {
            const int nb = buf ^ 1;
            float* pa = &As[nb][a_row * A_STRIDE + a_kcol];
            pa[0] = f2tf32(a0r.x); pa[1] = f2tf32(a0r.y);
            pa[2] = f2tf32(a0r.z); pa[3] = f2tf32(a0r.w);
            pa[4] = f2tf32(a1r.x); pa[5] = f2tf32(a1r.y);
            pa[6] = f2tf32(a1r.z); pa[7] = f2tf32(a1r.w);
            float* pb = &Bs[nb][b_krow * B_STRIDE + b_ncol];
            pb[0] = f2tf32(b0r.x); pb[1] = f2tf32(b0r.y);
            pb[2] = f2tf32(b0r.z); pb[3] = f2tf32(b0r.w);
            pb[4] = f2tf32(b1r.x); pb[5] = f2tf32(b1r.y);
            pb[6] = f2tf32(b1r.z); pb[7] = f2tf32(b1r.w);
        }
        __syncthreads();
        buf ^= 1;
    }

    // epilogue: scale by cw[s], write pre
    const float scale = __ldg(cw + s);
    float* dst = g_pre + (size_t)s * N_NODES * D_OUT;

#pragma unroll
    for (int mt = 0; mt < 4; mt++) {
        const int r0 = block_row + warp_m * 64 + mt * 16 + (lane >> 2);
        const int r1 = r0 + 8;
#pragma unroll
        for (int nt = 0; nt < 4; nt++) {
            const int col = block_col + warp_n * 32 + nt * 8 + 2 * (lane & 3);
            if (r0 < N_NODES) {
                float2 v = make_float2(c[mt][nt][0] * scale, c[mt][nt][1] * scale);
                *(float2*)(dst + (size_t)r0 * D_OUT + col) = v;
            }
            if (r1 < N_NODES) {
                float2 v = make_float2(c[mt][nt][2] * scale, c[mt][nt][3] * scale);
                *(float2*)(dst + (size_t)r1 * D_OUT + col) = v;
            }
        }
    }
}

// ---------------------------------------------------------------------------
// SpMM scatter: out[r] += v * pre[s][c].  64 lanes per nnz, one float4 each,
// vectorized global reduction (red.global.add.v4.f32).
// ---------------------------------------------------------------------------
__global__ __launch_bounds__(256) void spmm_kernel(
    const int*   __restrict__ rows,
    const int*   __restrict__ cols,
    const float* __restrict__ vals,
    float*       __restrict__ out)
{
    const int idx  = blockIdx.x * 4 + (threadIdx.x >> 6);  // nnz index in [0, S*NNZ)
    const int lane = threadIdx.x & 63;

    const int   r = rows[idx];
    const int   c = cols[idx];
    const float v = vals[idx];
    const int   s = idx / NNZ;

    const float4 p =
        *((const float4*)(g_pre + ((size_t)s * N_NODES + c) * D_OUT) + lane);

    float* dst = out + (size_t)r * D_OUT + lane * 4;
    asm volatile("red.global.add.v4.f32 [%0], {%1, %2, %3, %4};"
                 :: "l"(dst), "f"(p.x * v), "f"(p.y * v), "f"(p.z * v), "f"(p.w * v)
                 : "memory");
}

// ---------------------------------------------------------------------------
// Zero + ReLU
// ---------------------------------------------------------------------------
__global__ __launch_bounds__(256) void zero_kernel(float4* __restrict__ out)
{
    out[(size_t)blockIdx.x * 256 + threadIdx.x] = make_float4(0.f, 0.f, 0.f, 0.f);
}

__global__ __launch_bounds__(256) void relu_kernel(float4* __restrict__ out)
{
    const size_t i = (size_t)blockIdx.x * 256 + threadIdx.x;
    float4 v = out[i];
    v.x = fmaxf(v.x, 0.f);
    v.y = fmaxf(v.y, 0.f);
    v.z = fmaxf(v.z, 0.f);
    v.w = fmaxf(v.w, 0.f);
    out[i] = v;
}

// ---------------------------------------------------------------------------
// Launch
// ---------------------------------------------------------------------------
extern "C" void kernel_launch(void* const* d_in, const int* in_sizes, int n_in,
                              void* d_out, int out_size)
{
    const float* x    = (const float*)d_in[0];
    const float* W    = (const float*)d_in[1];
    const int*   rows = (const int*)d_in[2];
    const int*   cols = (const int*)d_in[3];
    const float* vals = (const float*)d_in[4];
    const float* cw   = (const float*)d_in[5];
    float*       out  = (float*)d_out;

    zero_kernel<<<12500, 256>>>((float4*)out);

    dim3 ggrid(D_OUT / BN, (N_NODES + BM - 1) / BM, S);  // (2, 391, 3)
    gemm_tf32_kernel<<<ggrid, 256>>>(x, W, cw);

    spmm_kernel<<<(S * NNZ) / 4, 256>>>(rows, cols, vals, out);

    relu_kernel<<<12500, 256>>>((float4*)out);
}